// round 13
// baseline (speedup 1.0000x reference)
#include <cuda_runtime.h>
#include <math.h>

// Problem constants (fixed by the reference)
#define N_BAGS   64
#define GRID_W   96
#define NCELLS   (N_BAGS * GRID_W * GRID_W)   // 589824
#define CAP      16        // bucket capacity; Poisson(0.222) => overflow ~impossible
#define NQ       512
#define NMEM     131072
#define DIM      256

#define NBLK     128
#define NTHR     1024                          // 131072 threads == NMEM rows
#define NTASK    (NQ * 8)                      // 4096 tasks == 4096 warps exactly

// Scratch: device globals (no runtime allocation allowed).
// g_cnt is zeroed each launch by a DMA memset node (cheap: copy engine).
__device__ unsigned g_cnt[NCELLS];
__device__ int      g_cell_items[NCELLS * CAP];

// ---- software grid barrier (128 CTAs, all co-resident by construction) ----
__device__ unsigned          g_bar_cnt;
__device__ volatile unsigned g_bar_gen;

__device__ __forceinline__ void grid_sync() {
    __syncthreads();
    if (threadIdx.x == 0) {
        __threadfence();
        unsigned gen = g_bar_gen;
        if (atomicAdd(&g_bar_cnt, 1u) == (unsigned)(gridDim.x - 1)) {
            g_bar_cnt = 0;
            __threadfence();
            g_bar_gen = gen + 1;               // release
        } else {
            while (g_bar_gen == gen) { }       // spin (volatile load)
        }
        __threadfence();
    }
    __syncthreads();
}

// ---------------------------------------------------------------------------
// Fused kernel, ONE grid barrier. Counters pre-zeroed by the memset node, so
// P1 is a single blind atomicAdd (+ guarded store): one L2 round trip less
// per row than the epoch scheme, on the chain that feeds the barrier.
//   Pre-barrier (overlapped): P1 coord loads (issued first), P2 prep
//     (task coords, q row, ||q|| reduce), P1 atomic+store, out[] zeroing.
//   Post-barrier: cnt + speculative items in ONE round trip -> rows -> exp.
// ---------------------------------------------------------------------------
__global__ void __launch_bounds__(NTHR, 1)
fused_kernel(const float* __restrict__ q,
             const float* __restrict__ memory,
             const int*   __restrict__ bag_idx,
             const int*   __restrict__ xc,
             const int*   __restrict__ yc,
             const int*   __restrict__ bag_idxs,
             const int*   __restrict__ xs,
             const int*   __restrict__ ys,
             float*       __restrict__ out) {
    const unsigned FULL = 0xFFFFFFFFu;
    int tid  = blockIdx.x * NTHR + threadIdx.x;          // 0 .. 131071
    int lane = threadIdx.x & 31;

    // ================= PRE-BARRIER (everything overlaps) =================

    // ---- P1 inputs first: this chain feeds the barrier ----
    int bi = bag_idxs[tid];
    int xi = xs[tid];
    int yi = ys[tid];

    // ---- P2 prep: one task per warp, depends only on kernel inputs ----
    int task = tid >> 5;                                 // 0 .. 4095
    int qi   = task >> 3;
    int nb   = task & 7;

    const float* qrow = q + qi * DIM + lane * 8;
    float4 a = *(const float4*)(qrow);
    float4 b = *(const float4*)(qrow + 4);

    int nidx = nb + (nb >= 4 ? 1 : 0);                   // 0..8 skip center
    int dxn = nidx % 3 - 1, dyn = nidx / 3 - 1;
    int xq = xc[qi] + dxn, yq = yc[qi] + dyn;
    bool valid = (xq >= 0) & (xq < GRID_W) & (yq >= 0) & (yq < GRID_W);
    int cell2 = (bag_idx[qi] * GRID_W + yq) * GRID_W + xq;

    // ---- P1: scatter my one memory row (single blind atomic); zero out ----
    if (tid < NQ) out[tid] = 0.0f;
    {
        int cell = (bi * GRID_W + yi) * GRID_W + xi;
        unsigned slot = atomicAdd(&g_cnt[cell], 1u);
        if (slot < CAP) g_cell_items[cell * CAP + slot] = tid;
    }

    // ---- ||q|| reduce (no memory deps; fills latency before barrier) ----
    float ss = a.x * a.x + a.y * a.y + a.z * a.z + a.w * a.w
             + b.x * b.x + b.y * b.y + b.z * b.z + b.w * b.w;
    #pragma unroll
    for (int o = 16; o; o >>= 1) ss += __shfl_xor_sync(FULL, ss, o);
    float inv = rsqrtf(ss) * 5.0f;                       // 1 / (||q|| * 0.2)

    grid_sync();

    // ================= POST-BARRIER (short chain) =================
    if (!valid) return;

    // cnt load and speculative item loads issue in the SAME round trip.
    // Items are garbage-tolerant: array holds in-range row indices (or
    // zero-init); masked by cnt before any use.
    unsigned word = g_cnt[cell2];
    int item = (lane < CAP) ? g_cell_items[cell2 * CAP + lane] : 0;

    int cnt = (int)word;
    if (cnt > CAP) cnt = CAP;
    if (cnt == 0) return;

    float s = 0.0f;
    for (int c0 = 0; c0 < cnt; c0 += 4) {
        int k = cnt - c0; if (k > 4) k = 4;
        float d[4];
        #pragma unroll
        for (int j = 0; j < 4; j++) {
            int ci = c0 + j; if (ci >= cnt) ci = cnt - 1;   // dup last (cached)
            int n = __shfl_sync(FULL, item, ci);
            const float* mr = memory + (size_t)n * DIM + lane * 8;
            float4 m0 = *(const float4*)(mr);
            float4 m1 = *(const float4*)(mr + 4);
            d[j] = a.x * m0.x + a.y * m0.y + a.z * m0.z + a.w * m0.w
                 + b.x * m1.x + b.y * m1.y + b.z * m1.z + b.w * m1.w;
        }
        #pragma unroll
        for (int o = 16; o; o >>= 1) {                   // 4 interleaved reductions
            d[0] += __shfl_xor_sync(FULL, d[0], o);
            d[1] += __shfl_xor_sync(FULL, d[1], o);
            d[2] += __shfl_xor_sync(FULL, d[2], o);
            d[3] += __shfl_xor_sync(FULL, d[3], o);
        }
        #pragma unroll
        for (int j = 0; j < 4; j++)
            if (j < k) s += __expf(d[j] * inv);
    }
    if (lane == 0) atomicAdd(&out[qi], s);
}

extern "C" void kernel_launch(void* const* d_in, const int* in_sizes, int n_in,
                              void* d_out, int out_size) {
    const float* q        = (const float*)d_in[0];   // [512, 256]
    const float* memory   = (const float*)d_in[1];   // [131072, 256]
    const int*   bag_idx  = (const int*)d_in[2];     // [512]
    const int*   x_coord  = (const int*)d_in[3];     // [512]
    const int*   y_coord  = (const int*)d_in[4];     // [512]
    const int*   bag_idxs = (const int*)d_in[5];     // [131072]
    const int*   x_coords = (const int*)d_in[6];     // [131072]
    const int*   y_coords = (const int*)d_in[7];     // [131072]
    float* out = (float*)d_out;                      // [512]

    // Zero the cell counters via DMA memset (copy engine; round-3 evidence:
    // memset + scatter together ~1.5us).
    void* cnt_ptr = nullptr;
    cudaGetSymbolAddress(&cnt_ptr, g_cnt);
    cudaMemsetAsync(cnt_ptr, 0, NCELLS * sizeof(unsigned));

    fused_kernel<<<NBLK, NTHR>>>(q, memory, bag_idx, x_coord, y_coord,
                                 bag_idxs, x_coords, y_coords, out);
}